// round 16
// baseline (speedup 1.0000x reference)
#include <cuda_runtime.h>

#define BATCH 4
#define DH 1024
#define DW 1024
#define FH 2048
#define FW 2048
#define RT2 0.70710678118654752f
#define C8F 0.92387953251128675f
#define S8F 0.38268343236508977f

__device__ float2 g_Y[BATCH * DH * DW];   // ifft_w(nnline_input), cols 0..512 stored (Hermitian)
__device__ float2 g_Z[BATCH * FH * DW];   // ifft_h,2048(input * s)  64 MB
__device__ float2 g_S[BATCH * DW];        // per-column phase * 1/FH
__device__ float2 g_TW[512];              // tw[j] = e^{-2pi i j/2048}

__device__ __forceinline__ float2 cmul(float2 a, float2 b) {
    return make_float2(a.x * b.x - a.y * b.y, a.x * b.y + a.y * b.x);
}
__device__ __forceinline__ float2 cadd(float2 a, float2 b) { return make_float2(a.x + b.x, a.y + b.y); }
__device__ __forceinline__ float2 csub(float2 a, float2 b) { return make_float2(a.x - b.x, a.y - b.y); }
template <bool INV> __device__ __forceinline__ float2 cmuli(float2 z) {      // * (∓i)
    return INV ? make_float2(-z.y, z.x) : make_float2(z.y, -z.x);
}
template <bool INV> __device__ __forceinline__ float2 cmulw8(float2 z) {     // * w16^2
    return INV ? make_float2(RT2 * (z.x - z.y), RT2 * (z.y + z.x))
               : make_float2(RT2 * (z.x + z.y), RT2 * (z.y - z.x));
}
template <bool INV> __device__ __forceinline__ float2 cmulw83(float2 z) {    // * w16^6
    return INV ? make_float2(-RT2 * (z.x + z.y), RT2 * (z.x - z.y))
               : make_float2(RT2 * (z.y - z.x), -RT2 * (z.x + z.y));
}
template <bool INV> __device__ __forceinline__ float2 cmulw16(float2 z) {    // * w16^1
    return INV ? make_float2(z.x * C8F - z.y * S8F, z.y * C8F + z.x * S8F)
               : make_float2(z.x * C8F + z.y * S8F, z.y * C8F - z.x * S8F);
}
template <bool INV> __device__ __forceinline__ float2 cmulw163(float2 z) {   // * w16^3
    return INV ? make_float2(z.x * S8F - z.y * C8F, z.y * S8F + z.x * C8F)
               : make_float2(z.x * S8F + z.y * C8F, z.y * S8F - z.x * C8F);
}
template <bool INV> __device__ __forceinline__ float2 cmulw169(float2 z) {   // * w16^9 = -w16^1
    float2 t = cmulw16<INV>(z);
    return make_float2(-t.x, -t.y);
}

__global__ void twiddle_init_kernel() {
    int j = blockIdx.x * blockDim.x + threadIdx.x;
    if (j < 512) {
        float s, c;
        sincospif(j * (1.0f / 1024.0f), &s, &c);
        g_TW[j] = make_float2(c, -s);
    }
}

__global__ void zero_fill_kernel(float* p, long long n) {
    long long i = (long long)blockIdx.x * blockDim.x + threadIdx.x;
    if (i < n) p[i] = 0.0f;
}

template <int NT>
__device__ __forceinline__ void load_tw(float2* stw) {
    for (int i = threadIdx.x; i < 512; i += NT) stw[i] = g_TW[i];
}

template <bool INV>
__device__ __forceinline__ void dft4(float2 a0, float2 a1, float2 a2, float2 a3,
                                     float2& o0, float2& o1, float2& o2, float2& o3) {
    float2 s0 = cadd(a0, a2), s1 = csub(a0, a2), s2 = cadd(a1, a3), s3 = csub(a1, a3);
    o0 = cadd(s0, s2); o1 = cadd(s1, cmuli<INV>(s3));
    o2 = csub(s0, s2); o3 = csub(s1, cmuli<INV>(s3));
}

template <bool INV>
__device__ __forceinline__ void dft8(float2 a0, float2 a1, float2 a2, float2 a3,
                                     float2 a4, float2 a5, float2 a6, float2 a7,
                                     float2* o) {
    float2 sE0 = cadd(a0, a4), sE1 = csub(a0, a4), sE2 = cadd(a2, a6), sE3 = csub(a2, a6);
    float2 E0 = cadd(sE0, sE2), E2 = csub(sE0, sE2);
    float2 E1 = cadd(sE1, cmuli<INV>(sE3)), E3 = csub(sE1, cmuli<INV>(sE3));
    float2 sO0 = cadd(a1, a5), sO1 = csub(a1, a5), sO2 = cadd(a3, a7), sO3 = csub(a3, a7);
    float2 O0 = cadd(sO0, sO2), O2 = csub(sO0, sO2);
    float2 O1 = cadd(sO1, cmuli<INV>(sO3)), O3 = csub(sO1, cmuli<INV>(sO3));
    float2 t0 = O0, t1 = cmulw8<INV>(O1), t2 = cmuli<INV>(O2), t3 = cmulw83<INV>(O3);
    o[0] = cadd(E0, t0); o[1] = cadd(E1, t1); o[2] = cadd(E2, t2); o[3] = cadd(E3, t3);
    o[4] = csub(E0, t0); o[5] = csub(E1, t1); o[6] = csub(E2, t2); o[7] = csub(E3, t3);
}

// radix-8 p=1 on zero-padded input (a4..a7 = 0), twiddle-free.
template <bool INV>
__device__ __forceinline__ void dft8_zpad(float2 a0, float2 a1, float2 a2, float2 a3, float2* o) {
    float2 E0 = cadd(a0, a2), E2 = csub(a0, a2);
    float2 E1 = cadd(a0, cmuli<INV>(a2)), E3 = csub(a0, cmuli<INV>(a2));
    float2 O0 = cadd(a1, a3), O2 = csub(a1, a3);
    float2 O1 = cadd(a1, cmuli<INV>(a3)), O3 = csub(a1, cmuli<INV>(a3));
    float2 t0 = O0, t1 = cmulw8<INV>(O1), t2 = cmuli<INV>(O2), t3 = cmulw83<INV>(O3);
    o[0] = cadd(E0, t0); o[1] = cadd(E1, t1); o[2] = cadd(E2, t2); o[3] = cadd(E3, t3);
    o[4] = csub(E0, t0); o[5] = csub(E1, t1); o[6] = csub(E2, t2); o[7] = csub(E3, t3);
}

// ---- In-place Stockham stages, layout buf[point*NCOL + col].
// Invariant: dst[R(j-k)+k+r*p] = DFT_R(a_q * w^q)_r,  w = e^{∓2pi i k/(R p)}.

template <int N, int NCOL, bool INV, int NT, int P>
__device__ __forceinline__ void r8_ip(float2* buf, const float2* tw) {
    constexpr int S = (N / 8) * NCOL;
    constexpr int U = S / NT;
    float2 v[U][8];
#pragma unroll
    for (int u = 0; u < U; u++) {
        int it = threadIdx.x + u * NT;
#pragma unroll
        for (int q = 0; q < 8; q++) v[u][q] = buf[it + q * S];
    }
    __syncthreads();
#pragma unroll
    for (int u = 0; u < U; u++) {
        int it = threadIdx.x + u * NT;
        int c = (NCOL == 1) ? 0 : (it & (NCOL - 1));
        int j = (NCOL == 1) ? it : (it / NCOL);
        int k = j & (P - 1);
        float2 w1 = tw[k * (256 / P)];
        if (INV) w1.y = -w1.y;
        float2 w2 = cmul(w1, w1), w3 = cmul(w2, w1), w4 = cmul(w2, w2);
        float2 w5 = cmul(w4, w1), w6 = cmul(w4, w2), w7 = cmul(w4, w3);
        float2 o[8];
        dft8<INV>(v[u][0], cmul(v[u][1], w1), cmul(v[u][2], w2), cmul(v[u][3], w3),
                  cmul(v[u][4], w4), cmul(v[u][5], w5), cmul(v[u][6], w6), cmul(v[u][7], w7), o);
        int base = (((j - k) << 3) + k) * NCOL + c;
#pragma unroll
        for (int r = 0; r < 8; r++) buf[base + r * P * NCOL] = o[r];
    }
    __syncthreads();
}

template <int N, int NCOL, bool INV, int NT, int P>
__device__ __forceinline__ void r16_ip(float2* buf, const float2* tw) {
    constexpr int S = (N / 16) * NCOL;
    constexpr int U = S / NT;
    static_assert(U >= 1, "r16 needs NT <= S");
    float2 v[U][16];
#pragma unroll
    for (int u = 0; u < U; u++) {
        int it = threadIdx.x + u * NT;
#pragma unroll
        for (int q = 0; q < 16; q++) v[u][q] = buf[it + q * S];
    }
    __syncthreads();
#pragma unroll
    for (int u = 0; u < U; u++) {
        int it = threadIdx.x + u * NT;
        int c = (NCOL == 1) ? 0 : (it & (NCOL - 1));
        int j = (NCOL == 1) ? it : (it / NCOL);
        int k = j & (P - 1);
        float2 w1 = tw[k * (128 / P)];
        if (INV) w1.y = -w1.y;
        float2 wq = w1;
        v[u][1] = cmul(v[u][1], wq);
#pragma unroll
        for (int q = 2; q < 16; q++) {
            wq = cmul(wq, w1);
            v[u][q] = cmul(v[u][q], wq);
        }
        float2 g[4][4];
#pragma unroll
        for (int n1 = 0; n1 < 4; n1++)
            dft4<INV>(v[u][n1], v[u][n1 + 4], v[u][n1 + 8], v[u][n1 + 12],
                      g[n1][0], g[n1][1], g[n1][2], g[n1][3]);
        g[1][1] = cmulw16<INV>(g[1][1]);  g[1][2] = cmulw8<INV>(g[1][2]);   g[1][3] = cmulw163<INV>(g[1][3]);
        g[2][1] = cmulw8<INV>(g[2][1]);   g[2][2] = cmuli<INV>(g[2][2]);   g[2][3] = cmulw83<INV>(g[2][3]);
        g[3][1] = cmulw163<INV>(g[3][1]); g[3][2] = cmulw83<INV>(g[3][2]); g[3][3] = cmulw169<INV>(g[3][3]);
        int base = (((j - k) << 4) + k) * NCOL + c;
        constexpr int PN = P * NCOL;
#pragma unroll
        for (int k2 = 0; k2 < 4; k2++) {
            float2 o0, o1, o2, o3;
            dft4<INV>(g[0][k2], g[1][k2], g[2][k2], g[3][k2], o0, o1, o2, o3);
            buf[base + k2 * PN]        = o0;
            buf[base + (k2 + 4) * PN]  = o1;
            buf[base + (k2 + 8) * PN]  = o2;
            buf[base + (k2 + 12) * PN] = o3;
        }
    }
    __syncthreads();
}

// Final r16 stage for N=2048, NCOL=4, NT=512, P=128 (k=j): transposed output
// buf[c*PITCH + point]. (complex-out k5 path)
template <bool INV, int PITCH>
__device__ __forceinline__ void r16_last_t(float2* buf, const float2* tw) {
    float2 v[16];
    const int it = threadIdx.x;
    const int c = it & 3, j = it >> 2;
#pragma unroll
    for (int q = 0; q < 16; q++) v[q] = buf[it + q * 512];
    __syncthreads();
    float2 w1 = tw[j];
    if (INV) w1.y = -w1.y;
    float2 wq = w1;
    v[1] = cmul(v[1], wq);
#pragma unroll
    for (int q = 2; q < 16; q++) {
        wq = cmul(wq, w1);
        v[q] = cmul(v[q], wq);
    }
    float2 g[4][4];
#pragma unroll
    for (int n1 = 0; n1 < 4; n1++)
        dft4<INV>(v[n1], v[n1 + 4], v[n1 + 8], v[n1 + 12],
                  g[n1][0], g[n1][1], g[n1][2], g[n1][3]);
    g[1][1] = cmulw16<INV>(g[1][1]);  g[1][2] = cmulw8<INV>(g[1][2]);   g[1][3] = cmulw163<INV>(g[1][3]);
    g[2][1] = cmulw8<INV>(g[2][1]);   g[2][2] = cmuli<INV>(g[2][2]);   g[2][3] = cmulw83<INV>(g[2][3]);
    g[3][1] = cmulw163<INV>(g[3][1]); g[3][2] = cmulw83<INV>(g[3][2]); g[3][3] = cmulw169<INV>(g[3][3]);
    float2* ob = buf + c * PITCH + j;
#pragma unroll
    for (int k2 = 0; k2 < 4; k2++) {
        float2 o0, o1, o2, o3;
        dft4<INV>(g[0][k2], g[1][k2], g[2][k2], g[3][k2], o0, o1, o2, o3);
        ob[k2 * 128]        = o0;
        ob[(k2 + 4) * 128]  = o1;
        ob[(k2 + 8) * 128]  = o2;
        ob[(k2 + 12) * 128] = o3;
    }
    __syncthreads();
}

// Final r8 stage for N=1024, NCOL=8, NT=512, P=128 (k=j): transposed output
// buf[c*PITCH + point]. (real-out k5 path)
template <bool INV, int PITCH>
__device__ __forceinline__ void r8_last_t8(float2* buf, const float2* tw) {
    float2 v[2][8];
#pragma unroll
    for (int u = 0; u < 2; u++) {
        int it = threadIdx.x + u * 512;
#pragma unroll
        for (int q = 0; q < 8; q++) v[u][q] = buf[it + q * 1024];
    }
    __syncthreads();
#pragma unroll
    for (int u = 0; u < 2; u++) {
        int it = threadIdx.x + u * 512;
        int c = it & 7, j = it >> 3;     // j < 128, k = j
        float2 w1 = tw[2 * j];           // e^{-2pi i j/1024}
        if (INV) w1.y = -w1.y;
        float2 w2 = cmul(w1, w1), w3 = cmul(w2, w1), w4 = cmul(w2, w2);
        float2 w5 = cmul(w4, w1), w6 = cmul(w4, w2), w7 = cmul(w4, w3);
        float2 o[8];
        dft8<INV>(v[u][0], cmul(v[u][1], w1), cmul(v[u][2], w2), cmul(v[u][3], w3),
                  cmul(v[u][4], w4), cmul(v[u][5], w5), cmul(v[u][6], w6), cmul(v[u][7], w7), o);
        float2* ob = buf + c * PITCH + j;
#pragma unroll
        for (int r = 0; r < 8; r++) ob[r * 128] = o[r];
    }
    __syncthreads();
}

// Hermitian unpack: W = transform(xa + i*xb), xa,xb real.
__device__ __forceinline__ float2 unpackA(float2 W, float2 Wm) {
    return make_float2(0.5f * (W.x + Wm.x), 0.5f * (W.y - Wm.y));
}
__device__ __forceinline__ float2 unpackB(float2 W, float2 Wm) {
    return make_float2(0.5f * (W.y + Wm.y), 0.5f * (Wm.x - W.x));
}

// K1: 8 real rows per block packed as 4 complex ifft_1024 (NCOL=4). Hermitian half store.
__global__ void __launch_bounds__(256) k1_row_ifft(const float* __restrict__ nn_in) {
    __shared__ float2 stw[512];
    __shared__ float2 buf[4096];
    const int row0 = 8 * blockIdx.x;
    load_tw<256>(stw);
    const float* basep = nn_in + (size_t)row0 * DW;
#pragma unroll
    for (int u = 0; u < 2; u++) {
        int it = threadIdx.x + u * 256;
        int c = it & 3, j = it >> 2;
        const float* rA = basep + (size_t)(2 * c) * DW;
        const float* rB = basep + (size_t)(2 * c + 1) * DW;
        float2 a[8];
#pragma unroll
        for (int q = 0; q < 8; q++)
            a[q] = make_float2(rA[j + q * 128] * (1.0f / DW), rB[j + q * 128] * (1.0f / DW));
        float2 o[8];
        dft8<true>(a[0], a[1], a[2], a[3], a[4], a[5], a[6], a[7], o);
#pragma unroll
        for (int r = 0; r < 8; r++) buf[(j * 8 + r) * 4 + c] = o[r];
    }
    __syncthreads();
    r16_ip<1024, 4, true, 256, 8>(buf, stw);
    r8_ip<1024, 4, true, 256, 128>(buf, stw);
    float2* outp = g_Y + (size_t)row0 * DW;
#pragma unroll
    for (int u = 0; u < 16; u++) {
        int it = threadIdx.x + u * 256;
        int c = it & 3, j = it >> 2;
        if (j <= 512) {
            int jm = (1024 - j) & 1023;
            float2 W = buf[j * 4 + c], Wm = buf[jm * 4 + c];
            outp[(size_t)(2 * c) * DW + j]     = unpackA(W, Wm);
            outp[(size_t)(2 * c + 1) * DW + j] = unpackB(W, Wm);
        }
    }
}

// K2: 8 cols per block (4 packed fft_1024). Y read from Hermitian half.
__global__ void __launch_bounds__(256) k2_col_fft_dot(const float* __restrict__ input) {
    __shared__ float2 stw[512];
    __shared__ float2 buf[4096];
    const int bg = blockIdx.x;
    const int b  = bg >> 7;
    const int w0 = (bg & 127) << 3;
    load_tw<256>(stw);
    const float* Xp = input + (size_t)b * DH * DW + w0;
#pragma unroll
    for (int u = 0; u < 2; u++) {
        int it = threadIdx.x + u * 256;
        int c = it & 3, j = it >> 2;
        float2 a[8];
#pragma unroll
        for (int q = 0; q < 8; q++)
            a[q] = *(const float2*)(Xp + (size_t)(j + q * 128) * DW + 2 * c);
        float2 o[8];
        dft8<false>(a[0], a[1], a[2], a[3], a[4], a[5], a[6], a[7], o);
#pragma unroll
        for (int r = 0; r < 8; r++) buf[(j * 8 + r) * 4 + c] = o[r];
    }
    __syncthreads();
    r16_ip<1024, 4, false, 256, 8>(buf, stw);
    r8_ip<1024, 4, false, 256, 128>(buf, stw);

    const float2* Yb = g_Y + (size_t)b * DH * DW;
    const int c = threadIdx.x & 7;
    const int w = w0 + c;
    const int we = (w <= 512) ? w : (1024 - w);
    const float cjs = (w <= 512) ? 1.0f : -1.0f;
    const int q = c >> 1, e = c & 1;
    float2 acc = make_float2(0.0f, 0.0f);
    for (int m = threadIdx.x >> 3; m < DH; m += 32) {
        int mm = (1024 - m) & 1023;
        float2 W = buf[m * 4 + q], Wm = buf[mm * 4 + q];
        float2 X = e ? unpackB(W, Wm) : unpackA(W, Wm);
        float2 Yv = Yb[(size_t)m * DW + we];
        Yv.y *= cjs;
        acc.x += Yv.x * X.x - Yv.y * X.y;
        acc.y += Yv.x * X.y + Yv.y * X.x;
    }
    __syncthreads();
    buf[threadIdx.x] = acc;
    __syncthreads();
    for (int s = 128; s >= 8; s >>= 1) {
        if (threadIdx.x < s) {
            buf[threadIdx.x].x += buf[threadIdx.x + s].x;
            buf[threadIdx.x].y += buf[threadIdx.x + s].y;
        }
        __syncthreads();
    }
    if (threadIdx.x < 8) {
        float2 T = buf[threadIdx.x];
        float r  = sqrtf(T.x * T.x + T.y * T.y);
        float2 sc = (r > 0.0f) ? make_float2(-T.y / r, T.x / r) : make_float2(1.0f, 0.0f);
        g_S[b * DW + w0 + threadIdx.x] = make_float2(sc.x * (1.0f / FH), sc.y * (1.0f / FH));
    }
}

// K4: 8 cols per block as 4 packed real ifft_2048 (NCOL=4, 512 threads).
__global__ void __launch_bounds__(512, 2) k4_col_ifft(const float* __restrict__ input) {
    extern __shared__ float2 sm[];
    float2* stw = sm;
    float2* buf = sm + 512;
    __shared__ float2 ssc[8];
    const int bg = blockIdx.x;
    const int b  = bg >> 7;
    const int w0 = (bg & 127) << 3;
    load_tw<512>(stw);
    if (threadIdx.x < 8) ssc[threadIdx.x] = g_S[b * DW + w0 + threadIdx.x];
    const float* Xp = input + (size_t)b * DH * DW + w0;
#pragma unroll
    for (int u = 0; u < 2; u++) {
        int it = threadIdx.x + u * 512;
        int c = it & 3, j = it >> 2;
        float2 a0 = *(const float2*)(Xp + (size_t)j * DW + 2 * c);
        float2 a1 = *(const float2*)(Xp + (size_t)(j + 256) * DW + 2 * c);
        float2 a2 = *(const float2*)(Xp + (size_t)(j + 512) * DW + 2 * c);
        float2 a3 = *(const float2*)(Xp + (size_t)(j + 768) * DW + 2 * c);
        float2 o[8];
        dft8_zpad<true>(a0, a1, a2, a3, o);
#pragma unroll
        for (int r = 0; r < 8; r++) buf[(j * 8 + r) * 4 + c] = o[r];
    }
    __syncthreads();
    r16_ip<2048, 4, true, 512, 8>(buf, stw);
    r16_ip<2048, 4, true, 512, 128>(buf, stw);
    float* Zf = (float*)(g_Z + (size_t)b * FH * DW + w0);
#pragma unroll
    for (int u = 0; u < 16; u++) {
        int it = threadIdx.x + u * 512;
        int q = it & 3, m = it >> 2;
        int mm = (2048 - m) & 2047;
        float2 W = buf[m * 4 + q], Wm = buf[mm * 4 + q];
        float2 A  = cmul(ssc[2 * q],     unpackA(W, Wm));
        float2 Bv = cmul(ssc[2 * q + 1], unpackB(W, Wm));
        *(float4*)(Zf + (size_t)m * (2 * DW) + 4 * q) = make_float4(A.x, A.y, Bv.x, Bv.y);
    }
}

// K5 (REAL OUT): 8 rows per block. Re(fft_2048(zeropad(z))) via one fft_1024:
//   G'_n = (v_n + conj(v_{1024-n})) + i*e^{-2pi i n/2048}*(v_n - conj(v_{1024-n}))
//   with v_0 = Re(z_0), v_n = z_n/2, v_1024 = 0.  Then
//   r_{2m} + i*r_{2m+1} = fft_1024(G')_m.
__global__ void __launch_bounds__(512, 2) k5_real_out(const float* __restrict__ nn_out,
                                                      const float* __restrict__ multi_out,
                                                      float* __restrict__ out) {
    extern __shared__ float2 sm[];
    float2* stw = sm;            // 512
    float2* buf = sm + 512;      // max(8192 interleaved, 8*1028 transposed) = 8224
    const int row0 = 8 * blockIdx.x;
    load_tw<512>(stw);
    __syncthreads();             // G-build below READS stw — must drain table writes
#pragma unroll
    for (int u = 0; u < 2; u++) {
        int it = threadIdx.x + u * 512;
        int c = it & 7, j = it >> 3;     // j < 128
        const float2* Zp = g_Z + (size_t)(row0 + c) * DW;
        float2 a[8];
#pragma unroll
        for (int q = 0; q < 8; q++) {
            int n = j + q * 128;
            float2 zn = Zp[n];
            float2 G;
            if (q == 0 && j == 0) {
                G = make_float2(zn.x, zn.x);           // v0*(1+i)
            } else {
                float2 zm = Zp[1024 - n];
                float2 h1 = make_float2(0.5f * (zn.x + zm.x), 0.5f * (zn.y - zm.y));
                float2 h2 = make_float2(0.5f * (zn.x - zm.x), 0.5f * (zn.y + zm.y));
                float2 twn;
                if (q < 4) twn = stw[n];                       // n < 512
                else { float2 t = stw[n - 512]; twn = make_float2(t.y, -t.x); }  // * -i
                float2 t2 = cmul(twn, h2);
                G = make_float2(h1.x - t2.y, h1.y + t2.x);     // h1 + i*t2
            }
            a[q] = G;
        }
        float2 o[8];
        dft8<false>(a[0], a[1], a[2], a[3], a[4], a[5], a[6], a[7], o);
#pragma unroll
        for (int r = 0; r < 8; r++) buf[(j * 8 + r) * 8 + c] = o[r];
    }
    __syncthreads();
    r16_ip<1024, 8, false, 512, 8>(buf, stw);
    r8_last_t8<false, 1028>(buf, stw);
    const float inv = 1.0f / 1.1f;  // 1/(1+RHO)
#pragma unroll
    for (int u = 0; u < 16; u++) {
        int it = threadIdx.x + u * 512;
        int c = it >> 10, m = it & 1023;           // row c, g-index m -> cols 2m,2m+1
        size_t off = (size_t)(row0 + c) * FW + 2 * m;
        float2 av = *(const float2*)(nn_out + off);
        float2 mv = *(const float2*)(multi_out + off);
        float2 g = buf[c * 1028 + m];              // r_{2m} = g.x, r_{2m+1} = g.y
        float mn0 = av.x - mv.x, mn1 = av.y - mv.y;
        float2 ov = make_float2(mn0 - (mn0 - g.x) * inv, mn1 - (mn1 - g.y) * inv);
        *(float2*)(out + off) = ov;
    }
}

// K5 (COMPLEX OUT, fallback): R14 version.
__global__ void __launch_bounds__(512, 2) k5_complex_out(const float* __restrict__ nn_out,
                                                         const float* __restrict__ multi_out,
                                                         float* __restrict__ out) {
    extern __shared__ float2 sm[];
    float2* stw = sm;
    float2* buf = sm + 512;
    const int row0 = 4 * blockIdx.x;
    load_tw<512>(stw);
#pragma unroll
    for (int u = 0; u < 2; u++) {
        int it = threadIdx.x + u * 512;
        int c = it & 3, j = it >> 2;
        const float2* Zp = g_Z + (size_t)(row0 + c) * DW;
        float2 o[8];
        dft8_zpad<false>(Zp[j], Zp[j + 256], Zp[j + 512], Zp[j + 768], o);
#pragma unroll
        for (int r = 0; r < 8; r++) buf[(j * 8 + r) * 4 + c] = o[r];
    }
    __syncthreads();
    r16_ip<2048, 4, false, 512, 8>(buf, stw);
    r16_last_t<false, 2052>(buf, stw);
    const float inv = 1.0f / 1.1f;
#pragma unroll
    for (int u = 0; u < 16; u++) {
        int it = threadIdx.x + u * 512;
        int c = it >> 11, j = it & 2047;
        size_t off = (size_t)(row0 + c) * FW + j;
        float mn = nn_out[off] - multi_out[off];
        float2 r = buf[c * 2052 + j];
        ((float2*)out)[off] = make_float2(mn - (mn - r.x) * inv, r.y * inv);
    }
}

extern "C" void kernel_launch(void* const* d_in, const int* in_sizes, int n_in,
                              void* d_out, int out_size) {
    // Input identification, unit-agnostic: frame tensors are 4x the data tensors.
    const float* frames[4] = {0, 0, 0, 0};
    const float* datas[4]  = {0, 0, 0, 0};
    int nf = 0, nd = 0;
    int first_is_frame = 0;
    long long mx = 0, mn = 0x7fffffffffffffffLL;
    for (int i = 0; i < n_in; i++) {
        long long s = in_sizes[i];
        if (s > mx) mx = s;
        if (s < mn) mn = s;
    }
    int ok = (n_in == 4) && (mx == 4 * mn) && (mn > 0);
    if (ok) {
        for (int i = 0; i < 4; i++) {
            if ((long long)in_sizes[i] == mx) { if (i == 0) first_is_frame = 1; if (nf < 4) frames[nf++] = (const float*)d_in[i]; }
            else if ((long long)in_sizes[i] == mn) { if (nd < 4) datas[nd++] = (const float*)d_in[i]; }
        }
        ok = (nf == 2 && nd == 2);
    }

    long long osz = out_size;
    bool complex_out = (osz == 2LL * BATCH * FH * FW) || (osz == 8LL * BATCH * FH * FW);

    if (!ok) {
        long long n = (long long)BATCH * FH * FW;
        zero_fill_kernel<<<(int)((n + 511) / 512), 512>>>((float*)d_out, n);
        return;
    }

    const float* input  = datas[0];
    const float* nn_in  = datas[1];
    const float* nn_out = first_is_frame ? frames[0] : frames[1];  // dict vs alphabetical
    const float* multi  = first_is_frame ? frames[1] : frames[0];

    const size_t smem_k4  = (size_t)(512 + 8192) * sizeof(float2);  // 69632 B
    const size_t smem_k5c = (size_t)(512 + 8208) * sizeof(float2);  // 69760 B
    const size_t smem_k5r = (size_t)(512 + 8224) * sizeof(float2);  // 69888 B
    cudaFuncSetAttribute(k4_col_ifft,    cudaFuncAttributeMaxDynamicSharedMemorySize, (int)smem_k4);
    cudaFuncSetAttribute(k5_complex_out, cudaFuncAttributeMaxDynamicSharedMemorySize, (int)smem_k5c);
    cudaFuncSetAttribute(k5_real_out,    cudaFuncAttributeMaxDynamicSharedMemorySize, (int)smem_k5r);

    twiddle_init_kernel<<<2, 256>>>();
    k1_row_ifft<<<BATCH * DH / 8, 256>>>(nn_in);
    k2_col_fft_dot<<<BATCH * (DW / 8), 256>>>(input);
    k4_col_ifft<<<BATCH * (DW / 8), 512, smem_k4>>>(input);
    if (complex_out)
        k5_complex_out<<<BATCH * FH / 4, 512, smem_k5c>>>(nn_out, multi, (float*)d_out);
    else
        k5_real_out<<<BATCH * FH / 8, 512, smem_k5r>>>(nn_out, multi, (float*)d_out);
}

// round 17
// speedup vs baseline: 1.1252x; 1.1252x over previous
#include <cuda_runtime.h>

#define BATCH 4
#define DH 1024
#define DW 1024
#define FH 2048
#define FW 2048
#define RT2 0.70710678118654752f
#define C8F 0.92387953251128675f
#define S8F 0.38268343236508977f

__device__ float2 g_Y[BATCH * DH * DW];   // ifft_w(nnline_input), cols 0..512 stored (Hermitian)
__device__ float2 g_Z[BATCH * FH * DW];   // ifft_h,2048(input * s)  64 MB
__device__ float2 g_S[BATCH * DW];        // per-column phase * 1/FH
__device__ float2 g_TW[512];              // tw[j] = e^{-2pi i j/2048}

__device__ __forceinline__ float2 cmul(float2 a, float2 b) {
    return make_float2(a.x * b.x - a.y * b.y, a.x * b.y + a.y * b.x);
}
__device__ __forceinline__ float2 cadd(float2 a, float2 b) { return make_float2(a.x + b.x, a.y + b.y); }
__device__ __forceinline__ float2 csub(float2 a, float2 b) { return make_float2(a.x - b.x, a.y - b.y); }
template <bool INV> __device__ __forceinline__ float2 cmuli(float2 z) {      // * (∓i)
    return INV ? make_float2(-z.y, z.x) : make_float2(z.y, -z.x);
}
template <bool INV> __device__ __forceinline__ float2 cmulw8(float2 z) {     // * w16^2
    return INV ? make_float2(RT2 * (z.x - z.y), RT2 * (z.y + z.x))
               : make_float2(RT2 * (z.x + z.y), RT2 * (z.y - z.x));
}
template <bool INV> __device__ __forceinline__ float2 cmulw83(float2 z) {    // * w16^6
    return INV ? make_float2(-RT2 * (z.x + z.y), RT2 * (z.x - z.y))
               : make_float2(RT2 * (z.y - z.x), -RT2 * (z.x + z.y));
}
template <bool INV> __device__ __forceinline__ float2 cmulw16(float2 z) {    // * w16^1
    return INV ? make_float2(z.x * C8F - z.y * S8F, z.y * C8F + z.x * S8F)
               : make_float2(z.x * C8F + z.y * S8F, z.y * C8F - z.x * S8F);
}
template <bool INV> __device__ __forceinline__ float2 cmulw163(float2 z) {   // * w16^3
    return INV ? make_float2(z.x * S8F - z.y * C8F, z.y * S8F + z.x * C8F)
               : make_float2(z.x * S8F + z.y * C8F, z.y * S8F - z.x * C8F);
}
template <bool INV> __device__ __forceinline__ float2 cmulw169(float2 z) {   // * w16^9 = -w16^1
    float2 t = cmulw16<INV>(z);
    return make_float2(-t.x, -t.y);
}

__global__ void twiddle_init_kernel() {
    int j = blockIdx.x * blockDim.x + threadIdx.x;
    if (j < 512) {
        float s, c;
        sincospif(j * (1.0f / 1024.0f), &s, &c);
        g_TW[j] = make_float2(c, -s);
    }
}

__global__ void zero_fill_kernel(float* p, long long n) {
    long long i = (long long)blockIdx.x * blockDim.x + threadIdx.x;
    if (i < n) p[i] = 0.0f;
}

template <int NT>
__device__ __forceinline__ void load_tw(float2* stw) {
    for (int i = threadIdx.x; i < 512; i += NT) stw[i] = g_TW[i];
}

template <bool INV>
__device__ __forceinline__ void dft4(float2 a0, float2 a1, float2 a2, float2 a3,
                                     float2& o0, float2& o1, float2& o2, float2& o3) {
    float2 s0 = cadd(a0, a2), s1 = csub(a0, a2), s2 = cadd(a1, a3), s3 = csub(a1, a3);
    o0 = cadd(s0, s2); o1 = cadd(s1, cmuli<INV>(s3));
    o2 = csub(s0, s2); o3 = csub(s1, cmuli<INV>(s3));
}

template <bool INV>
__device__ __forceinline__ void dft8(float2 a0, float2 a1, float2 a2, float2 a3,
                                     float2 a4, float2 a5, float2 a6, float2 a7,
                                     float2* o) {
    float2 sE0 = cadd(a0, a4), sE1 = csub(a0, a4), sE2 = cadd(a2, a6), sE3 = csub(a2, a6);
    float2 E0 = cadd(sE0, sE2), E2 = csub(sE0, sE2);
    float2 E1 = cadd(sE1, cmuli<INV>(sE3)), E3 = csub(sE1, cmuli<INV>(sE3));
    float2 sO0 = cadd(a1, a5), sO1 = csub(a1, a5), sO2 = cadd(a3, a7), sO3 = csub(a3, a7);
    float2 O0 = cadd(sO0, sO2), O2 = csub(sO0, sO2);
    float2 O1 = cadd(sO1, cmuli<INV>(sO3)), O3 = csub(sO1, cmuli<INV>(sO3));
    float2 t0 = O0, t1 = cmulw8<INV>(O1), t2 = cmuli<INV>(O2), t3 = cmulw83<INV>(O3);
    o[0] = cadd(E0, t0); o[1] = cadd(E1, t1); o[2] = cadd(E2, t2); o[3] = cadd(E3, t3);
    o[4] = csub(E0, t0); o[5] = csub(E1, t1); o[6] = csub(E2, t2); o[7] = csub(E3, t3);
}

// radix-8 p=1 on zero-padded input (a4..a7 = 0), twiddle-free.
template <bool INV>
__device__ __forceinline__ void dft8_zpad(float2 a0, float2 a1, float2 a2, float2 a3, float2* o) {
    float2 E0 = cadd(a0, a2), E2 = csub(a0, a2);
    float2 E1 = cadd(a0, cmuli<INV>(a2)), E3 = csub(a0, cmuli<INV>(a2));
    float2 O0 = cadd(a1, a3), O2 = csub(a1, a3);
    float2 O1 = cadd(a1, cmuli<INV>(a3)), O3 = csub(a1, cmuli<INV>(a3));
    float2 t0 = O0, t1 = cmulw8<INV>(O1), t2 = cmuli<INV>(O2), t3 = cmulw83<INV>(O3);
    o[0] = cadd(E0, t0); o[1] = cadd(E1, t1); o[2] = cadd(E2, t2); o[3] = cadd(E3, t3);
    o[4] = csub(E0, t0); o[5] = csub(E1, t1); o[6] = csub(E2, t2); o[7] = csub(E3, t3);
}

// ---- In-place Stockham stages, layout buf[point*NCOL + col].
// Invariant: dst[R(j-k)+k+r*p] = DFT_R(a_q * w^q)_r,  w = e^{∓2pi i k/(R p)}.

template <int N, int NCOL, bool INV, int NT, int P>
__device__ __forceinline__ void r8_ip(float2* buf, const float2* tw) {
    constexpr int S = (N / 8) * NCOL;
    constexpr int U = S / NT;
    float2 v[U][8];
#pragma unroll
    for (int u = 0; u < U; u++) {
        int it = threadIdx.x + u * NT;
#pragma unroll
        for (int q = 0; q < 8; q++) v[u][q] = buf[it + q * S];
    }
    __syncthreads();
#pragma unroll
    for (int u = 0; u < U; u++) {
        int it = threadIdx.x + u * NT;
        int c = (NCOL == 1) ? 0 : (it & (NCOL - 1));
        int j = (NCOL == 1) ? it : (it / NCOL);
        int k = j & (P - 1);
        float2 w1 = tw[k * (256 / P)];
        if (INV) w1.y = -w1.y;
        float2 w2 = cmul(w1, w1), w3 = cmul(w2, w1), w4 = cmul(w2, w2);
        float2 w5 = cmul(w4, w1), w6 = cmul(w4, w2), w7 = cmul(w4, w3);
        float2 o[8];
        dft8<INV>(v[u][0], cmul(v[u][1], w1), cmul(v[u][2], w2), cmul(v[u][3], w3),
                  cmul(v[u][4], w4), cmul(v[u][5], w5), cmul(v[u][6], w6), cmul(v[u][7], w7), o);
        int base = (((j - k) << 3) + k) * NCOL + c;
#pragma unroll
        for (int r = 0; r < 8; r++) buf[base + r * P * NCOL] = o[r];
    }
    __syncthreads();
}

template <int N, int NCOL, bool INV, int NT, int P>
__device__ __forceinline__ void r16_ip(float2* buf, const float2* tw) {
    constexpr int S = (N / 16) * NCOL;
    constexpr int U = S / NT;
    static_assert(U >= 1, "r16 needs NT <= S");
    float2 v[U][16];
#pragma unroll
    for (int u = 0; u < U; u++) {
        int it = threadIdx.x + u * NT;
#pragma unroll
        for (int q = 0; q < 16; q++) v[u][q] = buf[it + q * S];
    }
    __syncthreads();
#pragma unroll
    for (int u = 0; u < U; u++) {
        int it = threadIdx.x + u * NT;
        int c = (NCOL == 1) ? 0 : (it & (NCOL - 1));
        int j = (NCOL == 1) ? it : (it / NCOL);
        int k = j & (P - 1);
        float2 w1 = tw[k * (128 / P)];
        if (INV) w1.y = -w1.y;
        float2 wq = w1;
        v[u][1] = cmul(v[u][1], wq);
#pragma unroll
        for (int q = 2; q < 16; q++) {
            wq = cmul(wq, w1);
            v[u][q] = cmul(v[u][q], wq);
        }
        float2 g[4][4];
#pragma unroll
        for (int n1 = 0; n1 < 4; n1++)
            dft4<INV>(v[u][n1], v[u][n1 + 4], v[u][n1 + 8], v[u][n1 + 12],
                      g[n1][0], g[n1][1], g[n1][2], g[n1][3]);
        g[1][1] = cmulw16<INV>(g[1][1]);  g[1][2] = cmulw8<INV>(g[1][2]);   g[1][3] = cmulw163<INV>(g[1][3]);
        g[2][1] = cmulw8<INV>(g[2][1]);   g[2][2] = cmuli<INV>(g[2][2]);   g[2][3] = cmulw83<INV>(g[2][3]);
        g[3][1] = cmulw163<INV>(g[3][1]); g[3][2] = cmulw83<INV>(g[3][2]); g[3][3] = cmulw169<INV>(g[3][3]);
        int base = (((j - k) << 4) + k) * NCOL + c;
        constexpr int PN = P * NCOL;
#pragma unroll
        for (int k2 = 0; k2 < 4; k2++) {
            float2 o0, o1, o2, o3;
            dft4<INV>(g[0][k2], g[1][k2], g[2][k2], g[3][k2], o0, o1, o2, o3);
            buf[base + k2 * PN]        = o0;
            buf[base + (k2 + 4) * PN]  = o1;
            buf[base + (k2 + 8) * PN]  = o2;
            buf[base + (k2 + 12) * PN] = o3;
        }
    }
    __syncthreads();
}

// Final r16 stage for N=2048, NCOL=4, NT=512, P=128 (k=j): transposed output
// buf[c*PITCH + point]. (complex-out k5 path)
template <bool INV, int PITCH>
__device__ __forceinline__ void r16_last_t(float2* buf, const float2* tw) {
    float2 v[16];
    const int it = threadIdx.x;
    const int c = it & 3, j = it >> 2;
#pragma unroll
    for (int q = 0; q < 16; q++) v[q] = buf[it + q * 512];
    __syncthreads();
    float2 w1 = tw[j];
    if (INV) w1.y = -w1.y;
    float2 wq = w1;
    v[1] = cmul(v[1], wq);
#pragma unroll
    for (int q = 2; q < 16; q++) {
        wq = cmul(wq, w1);
        v[q] = cmul(v[q], wq);
    }
    float2 g[4][4];
#pragma unroll
    for (int n1 = 0; n1 < 4; n1++)
        dft4<INV>(v[n1], v[n1 + 4], v[n1 + 8], v[n1 + 12],
                  g[n1][0], g[n1][1], g[n1][2], g[n1][3]);
    g[1][1] = cmulw16<INV>(g[1][1]);  g[1][2] = cmulw8<INV>(g[1][2]);   g[1][3] = cmulw163<INV>(g[1][3]);
    g[2][1] = cmulw8<INV>(g[2][1]);   g[2][2] = cmuli<INV>(g[2][2]);   g[2][3] = cmulw83<INV>(g[2][3]);
    g[3][1] = cmulw163<INV>(g[3][1]); g[3][2] = cmulw83<INV>(g[3][2]); g[3][3] = cmulw169<INV>(g[3][3]);
    float2* ob = buf + c * PITCH + j;
#pragma unroll
    for (int k2 = 0; k2 < 4; k2++) {
        float2 o0, o1, o2, o3;
        dft4<INV>(g[0][k2], g[1][k2], g[2][k2], g[3][k2], o0, o1, o2, o3);
        ob[k2 * 128]        = o0;
        ob[(k2 + 4) * 128]  = o1;
        ob[(k2 + 8) * 128]  = o2;
        ob[(k2 + 12) * 128] = o3;
    }
    __syncthreads();
}

// Final r8 stage for N=1024, NCOL=8, NT=512, P=128 (k=j): transposed output
// buf[c*PITCH + point]. (real-out k5 path)
template <bool INV, int PITCH>
__device__ __forceinline__ void r8_last_t8(float2* buf, const float2* tw) {
    float2 v[2][8];
#pragma unroll
    for (int u = 0; u < 2; u++) {
        int it = threadIdx.x + u * 512;
#pragma unroll
        for (int q = 0; q < 8; q++) v[u][q] = buf[it + q * 1024];
    }
    __syncthreads();
#pragma unroll
    for (int u = 0; u < 2; u++) {
        int it = threadIdx.x + u * 512;
        int c = it & 7, j = it >> 3;     // j < 128, k = j
        float2 w1 = tw[2 * j];           // e^{-2pi i j/1024}
        if (INV) w1.y = -w1.y;
        float2 w2 = cmul(w1, w1), w3 = cmul(w2, w1), w4 = cmul(w2, w2);
        float2 w5 = cmul(w4, w1), w6 = cmul(w4, w2), w7 = cmul(w4, w3);
        float2 o[8];
        dft8<INV>(v[u][0], cmul(v[u][1], w1), cmul(v[u][2], w2), cmul(v[u][3], w3),
                  cmul(v[u][4], w4), cmul(v[u][5], w5), cmul(v[u][6], w6), cmul(v[u][7], w7), o);
        float2* ob = buf + c * PITCH + j;
#pragma unroll
        for (int r = 0; r < 8; r++) ob[r * 128] = o[r];
    }
    __syncthreads();
}

// Hermitian unpack: W = transform(xa + i*xb), xa,xb real.
__device__ __forceinline__ float2 unpackA(float2 W, float2 Wm) {
    return make_float2(0.5f * (W.x + Wm.x), 0.5f * (W.y - Wm.y));
}
__device__ __forceinline__ float2 unpackB(float2 W, float2 Wm) {
    return make_float2(0.5f * (W.y + Wm.y), 0.5f * (Wm.x - W.x));
}

// K1: 8 real rows per block packed as 4 complex ifft_1024 (NCOL=4). Hermitian half store.
__global__ void __launch_bounds__(256) k1_row_ifft(const float* __restrict__ nn_in) {
    __shared__ float2 stw[512];
    __shared__ float2 buf[4096];
    const int row0 = 8 * blockIdx.x;
    load_tw<256>(stw);
    const float* basep = nn_in + (size_t)row0 * DW;
#pragma unroll
    for (int u = 0; u < 2; u++) {
        int it = threadIdx.x + u * 256;
        int c = it & 3, j = it >> 2;
        const float* rA = basep + (size_t)(2 * c) * DW;
        const float* rB = basep + (size_t)(2 * c + 1) * DW;
        float2 a[8];
#pragma unroll
        for (int q = 0; q < 8; q++)
            a[q] = make_float2(rA[j + q * 128] * (1.0f / DW), rB[j + q * 128] * (1.0f / DW));
        float2 o[8];
        dft8<true>(a[0], a[1], a[2], a[3], a[4], a[5], a[6], a[7], o);
#pragma unroll
        for (int r = 0; r < 8; r++) buf[(j * 8 + r) * 4 + c] = o[r];
    }
    __syncthreads();
    r16_ip<1024, 4, true, 256, 8>(buf, stw);
    r8_ip<1024, 4, true, 256, 128>(buf, stw);
    float2* outp = g_Y + (size_t)row0 * DW;
#pragma unroll
    for (int u = 0; u < 16; u++) {
        int it = threadIdx.x + u * 256;
        int c = it & 3, j = it >> 2;
        if (j <= 512) {
            int jm = (1024 - j) & 1023;
            float2 W = buf[j * 4 + c], Wm = buf[jm * 4 + c];
            outp[(size_t)(2 * c) * DW + j]     = unpackA(W, Wm);
            outp[(size_t)(2 * c + 1) * DW + j] = unpackB(W, Wm);
        }
    }
}

// K2: 8 cols per block (4 packed fft_1024). Y read from Hermitian half.
__global__ void __launch_bounds__(256) k2_col_fft_dot(const float* __restrict__ input) {
    __shared__ float2 stw[512];
    __shared__ float2 buf[4096];
    const int bg = blockIdx.x;
    const int b  = bg >> 7;
    const int w0 = (bg & 127) << 3;
    load_tw<256>(stw);
    const float* Xp = input + (size_t)b * DH * DW + w0;
#pragma unroll
    for (int u = 0; u < 2; u++) {
        int it = threadIdx.x + u * 256;
        int c = it & 3, j = it >> 2;
        float2 a[8];
#pragma unroll
        for (int q = 0; q < 8; q++)
            a[q] = *(const float2*)(Xp + (size_t)(j + q * 128) * DW + 2 * c);
        float2 o[8];
        dft8<false>(a[0], a[1], a[2], a[3], a[4], a[5], a[6], a[7], o);
#pragma unroll
        for (int r = 0; r < 8; r++) buf[(j * 8 + r) * 4 + c] = o[r];
    }
    __syncthreads();
    r16_ip<1024, 4, false, 256, 8>(buf, stw);
    r8_ip<1024, 4, false, 256, 128>(buf, stw);

    const float2* Yb = g_Y + (size_t)b * DH * DW;
    const int c = threadIdx.x & 7;
    const int w = w0 + c;
    const int we = (w <= 512) ? w : (1024 - w);
    const float cjs = (w <= 512) ? 1.0f : -1.0f;
    const int q = c >> 1, e = c & 1;
    float2 acc = make_float2(0.0f, 0.0f);
    for (int m = threadIdx.x >> 3; m < DH; m += 32) {
        int mm = (1024 - m) & 1023;
        float2 W = buf[m * 4 + q], Wm = buf[mm * 4 + q];
        float2 X = e ? unpackB(W, Wm) : unpackA(W, Wm);
        float2 Yv = Yb[(size_t)m * DW + we];
        Yv.y *= cjs;
        acc.x += Yv.x * X.x - Yv.y * X.y;
        acc.y += Yv.x * X.y + Yv.y * X.x;
    }
    __syncthreads();
    buf[threadIdx.x] = acc;
    __syncthreads();
    for (int s = 128; s >= 8; s >>= 1) {
        if (threadIdx.x < s) {
            buf[threadIdx.x].x += buf[threadIdx.x + s].x;
            buf[threadIdx.x].y += buf[threadIdx.x + s].y;
        }
        __syncthreads();
    }
    if (threadIdx.x < 8) {
        float2 T = buf[threadIdx.x];
        float r  = sqrtf(T.x * T.x + T.y * T.y);
        float2 sc = (r > 0.0f) ? make_float2(-T.y / r, T.x / r) : make_float2(1.0f, 0.0f);
        g_S[b * DW + w0 + threadIdx.x] = make_float2(sc.x * (1.0f / FH), sc.y * (1.0f / FH));
    }
}

// K4: 8 cols per block as 4 packed real ifft_2048 (NCOL=4, 512 threads).
__global__ void __launch_bounds__(512, 2) k4_col_ifft(const float* __restrict__ input) {
    extern __shared__ float2 sm[];
    float2* stw = sm;
    float2* buf = sm + 512;
    __shared__ float2 ssc[8];
    const int bg = blockIdx.x;
    const int b  = bg >> 7;
    const int w0 = (bg & 127) << 3;
    load_tw<512>(stw);
    if (threadIdx.x < 8) ssc[threadIdx.x] = g_S[b * DW + w0 + threadIdx.x];
    const float* Xp = input + (size_t)b * DH * DW + w0;
#pragma unroll
    for (int u = 0; u < 2; u++) {
        int it = threadIdx.x + u * 512;
        int c = it & 3, j = it >> 2;
        float2 a0 = *(const float2*)(Xp + (size_t)j * DW + 2 * c);
        float2 a1 = *(const float2*)(Xp + (size_t)(j + 256) * DW + 2 * c);
        float2 a2 = *(const float2*)(Xp + (size_t)(j + 512) * DW + 2 * c);
        float2 a3 = *(const float2*)(Xp + (size_t)(j + 768) * DW + 2 * c);
        float2 o[8];
        dft8_zpad<true>(a0, a1, a2, a3, o);
#pragma unroll
        for (int r = 0; r < 8; r++) buf[(j * 8 + r) * 4 + c] = o[r];
    }
    __syncthreads();
    r16_ip<2048, 4, true, 512, 8>(buf, stw);
    r16_ip<2048, 4, true, 512, 128>(buf, stw);
    float* Zf = (float*)(g_Z + (size_t)b * FH * DW + w0);
#pragma unroll
    for (int u = 0; u < 16; u++) {
        int it = threadIdx.x + u * 512;
        int q = it & 3, m = it >> 2;
        int mm = (2048 - m) & 2047;
        float2 W = buf[m * 4 + q], Wm = buf[mm * 4 + q];
        float2 A  = cmul(ssc[2 * q],     unpackA(W, Wm));
        float2 Bv = cmul(ssc[2 * q + 1], unpackB(W, Wm));
        *(float4*)(Zf + (size_t)m * (2 * DW) + 4 * q) = make_float4(A.x, A.y, Bv.x, Bv.y);
    }
}

// K5 (REAL OUT): 8 rows per block, half-size transform with SMEM-STAGED z.
//   r_{2m} + i*r_{2m+1} = fft_1024(G')_m,
//   G'_n = h1 + i*tw_n*h2,  h1 = v_n + conj(v_{1024-n}), h2 = v_n - conj(v_{1024-n}),
//   v_0 = Re(z_0), v_n = z_n/2 (folded into h1,h2 via 0.5f), v_1024 = 0.
// z rows staged into smem once (coalesced); G-build reads smem only.
__global__ void __launch_bounds__(512, 2) k5_real_out(const float* __restrict__ nn_out,
                                                      const float* __restrict__ multi_out,
                                                      float* __restrict__ out) {
    extern __shared__ float2 sm[];
    float2* stw  = sm;            // 512
    float2* zbuf = sm + 512;      // 9216: z staged as zbuf[n*9 + c], then reused as FFT buf
    const int row0 = 8 * blockIdx.x;
    load_tw<512>(stw);
    // Stage all 8 rows of g_Z, fully coalesced (g_Z read exactly once).
#pragma unroll
    for (int u = 0; u < 16; u++) {
        int it = threadIdx.x + u * 512;
        int c = it >> 10, n = it & 1023;
        zbuf[n * 9 + c] = g_Z[((size_t)(row0 + c)) * DW + n];
    }
    __syncthreads();
    // G-build from smem + fused first radix-8 stage; hold outputs across barrier.
    float2 oa[2][8];
#pragma unroll
    for (int u = 0; u < 2; u++) {
        int it = threadIdx.x + u * 512;
        int c = it & 7, j = it >> 3;     // j in [0,128)
        float2 a[8];
#pragma unroll
        for (int q = 0; q < 8; q++) {
            int n = j + q * 128;
            float2 zn = zbuf[n * 9 + c];
            float2 G;
            if (q == 0 && j == 0) {
                G = make_float2(zn.x, zn.x);           // v0*(1+i)
            } else {
                float2 zm = zbuf[(1024 - n) * 9 + c];
                float2 h1 = make_float2(0.5f * (zn.x + zm.x), 0.5f * (zn.y - zm.y));
                float2 h2 = make_float2(0.5f * (zn.x - zm.x), 0.5f * (zn.y + zm.y));
                float2 twn;
                if (q < 4) twn = stw[n];                       // n < 512
                else { float2 t = stw[n - 512]; twn = make_float2(t.y, -t.x); }  // * -i
                float2 t2 = cmul(twn, h2);
                G = make_float2(h1.x - t2.y, h1.y + t2.x);     // h1 + i*t2
            }
            a[q] = G;
        }
        dft8<false>(a[0], a[1], a[2], a[3], a[4], a[5], a[6], a[7], oa[u]);
    }
    __syncthreads();   // all z reads complete before in-place overwrite
#pragma unroll
    for (int u = 0; u < 2; u++) {
        int it = threadIdx.x + u * 512;
        int c = it & 7, j = it >> 3;
#pragma unroll
        for (int r = 0; r < 8; r++) zbuf[(j * 8 + r) * 8 + c] = oa[u][r];
    }
    __syncthreads();
    r16_ip<1024, 8, false, 512, 8>(zbuf, stw);
    r8_last_t8<false, 1028>(zbuf, stw);
    const float inv = 1.0f / 1.1f;  // 1/(1+RHO)
#pragma unroll
    for (int u = 0; u < 16; u++) {
        int it = threadIdx.x + u * 512;
        int c = it >> 10, m = it & 1023;           // row c, g-index m -> cols 2m,2m+1
        size_t off = (size_t)(row0 + c) * FW + 2 * m;
        float2 av = *(const float2*)(nn_out + off);
        float2 mv = *(const float2*)(multi_out + off);
        float2 g = zbuf[c * 1028 + m];             // r_{2m} = g.x, r_{2m+1} = g.y
        float mn0 = av.x - mv.x, mn1 = av.y - mv.y;
        float2 ov = make_float2(mn0 - (mn0 - g.x) * inv, mn1 - (mn1 - g.y) * inv);
        *(float2*)(out + off) = ov;
    }
}

// K5 (COMPLEX OUT, fallback): R14 version.
__global__ void __launch_bounds__(512, 2) k5_complex_out(const float* __restrict__ nn_out,
                                                         const float* __restrict__ multi_out,
                                                         float* __restrict__ out) {
    extern __shared__ float2 sm[];
    float2* stw = sm;
    float2* buf = sm + 512;
    const int row0 = 4 * blockIdx.x;
    load_tw<512>(stw);
#pragma unroll
    for (int u = 0; u < 2; u++) {
        int it = threadIdx.x + u * 512;
        int c = it & 3, j = it >> 2;
        const float2* Zp = g_Z + (size_t)(row0 + c) * DW;
        float2 o[8];
        dft8_zpad<false>(Zp[j], Zp[j + 256], Zp[j + 512], Zp[j + 768], o);
#pragma unroll
        for (int r = 0; r < 8; r++) buf[(j * 8 + r) * 4 + c] = o[r];
    }
    __syncthreads();
    r16_ip<2048, 4, false, 512, 8>(buf, stw);
    r16_last_t<false, 2052>(buf, stw);
    const float inv = 1.0f / 1.1f;
#pragma unroll
    for (int u = 0; u < 16; u++) {
        int it = threadIdx.x + u * 512;
        int c = it >> 11, j = it & 2047;
        size_t off = (size_t)(row0 + c) * FW + j;
        float mn = nn_out[off] - multi_out[off];
        float2 r = buf[c * 2052 + j];
        ((float2*)out)[off] = make_float2(mn - (mn - r.x) * inv, r.y * inv);
    }
}

extern "C" void kernel_launch(void* const* d_in, const int* in_sizes, int n_in,
                              void* d_out, int out_size) {
    // Input identification, unit-agnostic: frame tensors are 4x the data tensors.
    const float* frames[4] = {0, 0, 0, 0};
    const float* datas[4]  = {0, 0, 0, 0};
    int nf = 0, nd = 0;
    int first_is_frame = 0;
    long long mx = 0, mn = 0x7fffffffffffffffLL;
    for (int i = 0; i < n_in; i++) {
        long long s = in_sizes[i];
        if (s > mx) mx = s;
        if (s < mn) mn = s;
    }
    int ok = (n_in == 4) && (mx == 4 * mn) && (mn > 0);
    if (ok) {
        for (int i = 0; i < 4; i++) {
            if ((long long)in_sizes[i] == mx) { if (i == 0) first_is_frame = 1; if (nf < 4) frames[nf++] = (const float*)d_in[i]; }
            else if ((long long)in_sizes[i] == mn) { if (nd < 4) datas[nd++] = (const float*)d_in[i]; }
        }
        ok = (nf == 2 && nd == 2);
    }

    long long osz = out_size;
    bool complex_out = (osz == 2LL * BATCH * FH * FW) || (osz == 8LL * BATCH * FH * FW);

    if (!ok) {
        long long n = (long long)BATCH * FH * FW;
        zero_fill_kernel<<<(int)((n + 511) / 512), 512>>>((float*)d_out, n);
        return;
    }

    const float* input  = datas[0];
    const float* nn_in  = datas[1];
    const float* nn_out = first_is_frame ? frames[0] : frames[1];  // dict vs alphabetical
    const float* multi  = first_is_frame ? frames[1] : frames[0];

    const size_t smem_k4  = (size_t)(512 + 8192) * sizeof(float2);  // 69632 B
    const size_t smem_k5c = (size_t)(512 + 8208) * sizeof(float2);  // 69760 B
    const size_t smem_k5r = (size_t)(512 + 9216) * sizeof(float2);  // 77824 B
    cudaFuncSetAttribute(k4_col_ifft,    cudaFuncAttributeMaxDynamicSharedMemorySize, (int)smem_k4);
    cudaFuncSetAttribute(k5_complex_out, cudaFuncAttributeMaxDynamicSharedMemorySize, (int)smem_k5c);
    cudaFuncSetAttribute(k5_real_out,    cudaFuncAttributeMaxDynamicSharedMemorySize, (int)smem_k5r);

    twiddle_init_kernel<<<2, 256>>>();
    k1_row_ifft<<<BATCH * DH / 8, 256>>>(nn_in);
    k2_col_fft_dot<<<BATCH * (DW / 8), 256>>>(input);
    k4_col_ifft<<<BATCH * (DW / 8), 512, smem_k4>>>(input);
    if (complex_out)
        k5_complex_out<<<BATCH * FH / 4, 512, smem_k5c>>>(nn_out, multi, (float*)d_out);
    else
        k5_real_out<<<BATCH * FH / 8, 512, smem_k5r>>>(nn_out, multi, (float*)d_out);
}